// round 17
// baseline (speedup 1.0000x reference)
#include <cuda_runtime.h>
#include <cstdint>

#define SEQ    2048
#define BATCH  2
#define HID    2048
#define NPH    16
#define HN     128
#define MTOT   (SEQ*BATCH)     // 4096
#define QKVN   (3*HID)         // 6144
#define NHEADS (BATCH*NPH)     // 32
#define ATT_SCALE (1.0f/11.313708498984761f)
#define RS     (BATCH*QKVN)    // 12288
#define NXBLK  (SEQ/128)       // 16 score col-blocks per row

// Scratch (device globals; no allocation allowed anywhere)
__device__ float g_qkv[(size_t)MTOT * QKVN];
__device__ float g_scores[(size_t)NHEADS * SEQ * SEQ];   // holds exp(s) after scores pass
__device__ float g_vT[(size_t)NHEADS * HN * SEQ];
__device__ float g_ctx[(size_t)MTOT * HID];
__device__ float g_hid[(size_t)MTOT * HID];
__device__ float g_wqkv[(size_t)QKVN * HID];
__device__ float g_wout[(size_t)HID * HID];
__device__ float g_psum[(size_t)NHEADS * SEQ * NXBLK];   // per-block exp row sums
__device__ float g_rowinv[(size_t)NHEADS * SEQ];         // 1 / full row sum

__device__ __forceinline__ uint32_t f2tf32(float x) {
    uint32_t r; asm("cvt.rna.tf32.f32 %0, %1;" : "=r"(r) : "f"(x)); return r;
}
__device__ __forceinline__ float f2tf32f(float x) {
    return __uint_as_float(f2tf32(x));
}
__device__ __forceinline__ void mma_tf32(float* d, const uint32_t* a, const uint32_t* b) {
    asm volatile(
        "mma.sync.aligned.m16n8k8.row.col.f32.tf32.tf32.f32 "
        "{%0,%1,%2,%3}, {%4,%5,%6,%7}, {%8,%9}, {%0,%1,%2,%3};"
        : "+f"(d[0]), "+f"(d[1]), "+f"(d[2]), "+f"(d[3])
        : "r"(a[0]), "r"(a[1]), "r"(a[2]), "r"(a[3]), "r"(b[0]), "r"(b[1]));
}
__device__ __forceinline__ void ldsm4(uint32_t& r0, uint32_t& r1, uint32_t& r2, uint32_t& r3,
                                      uint32_t addr) {
    asm volatile("ldmatrix.sync.aligned.m8n8.x4.shared.b16 {%0,%1,%2,%3}, [%4];"
                 : "=r"(r0), "=r"(r1), "=r"(r2), "=r"(r3) : "r"(addr));
}
__device__ __forceinline__ void cp16(uint32_t dst, const void* src) {
    asm volatile("cp.async.cg.shared.global [%0], [%1], 16;" :: "r"(dst), "l"(src));
}

// ---------------------------------------------------------------------------
// NT GEMM: C[m,n] = alpha * sum_k A[m,k] * B[n,k].  BM=BN=128, BK=32,
// 256 thr (8 warps 2x4), warp tile 64x32, 3-stage cp.async ring, pitch 36.
// Slice order inside each K-tile is ROTATED PER WARP ((s+warp)&3) so the four
// warps of an SMSP hit their LDSM dependency walls at different times and the
// tensor pipe stays covered (de-correlates post-barrier stalls).
// MODE 0: plain fp32 out.
// MODE 1: out rounded to tf32 (feeds another GEMM).
// MODE 2: out = tf32(exp(alpha*acc)); per-CTA row sums of exp -> psum.
// MODE 3: out = tf32(acc * rowinv[row])  (row-normalized, feeds out-proj).
// ---------------------------------------------------------------------------
#define PITCH 36
#define STAGE_BYTES (128 * PITCH * 4)
#define GEMM_SMEM   (6 * STAGE_BYTES)

template <int MODE>
__global__ void __launch_bounds__(256, 2)
gemm_nt(const float* __restrict__ A, int lda, long sAz,
        const float* __restrict__ B, int ldb, long sBz,
        float*       __restrict__ C, int ldc, long sCz,
        int K, float alpha,
        float* __restrict__ psum, const float* __restrict__ rowinv)
{
    extern __shared__ __align__(16) char smem[];
    const uint32_t sb = (uint32_t)__cvta_generic_to_shared(smem);

    const int z = blockIdx.z;
    A += (long)z * sAz; B += (long)z * sBz; C += (long)z * sCz;

    const int m0 = blockIdx.y * 128;
    const int n0 = blockIdx.x * 128;
    const int t    = threadIdx.x;
    const int lane = t & 31;
    const int warp = t >> 5;
    const int wm = (warp >> 2) * 64;
    const int wn = (warp & 3)  * 32;
    const int gid = lane >> 2;
    const int tg  = lane & 3;
    const int sub = lane >> 3;
    const int lr  = lane & 7;

    const int crow = t >> 3;            // 0..31 (+32*i)
    const int ccol = (t & 7) * 4;       // 0,4,...,28

    float acc[4][4][4];
#pragma unroll
    for (int i = 0; i < 4; i++)
#pragma unroll
        for (int j = 0; j < 4; j++)
#pragma unroll
            for (int r = 0; r < 4; r++) acc[i][j][r] = 0.0f;

    auto issue = [&](int kt) {
        const int st = kt % 3;
        const int k0 = kt * 32;
        const uint32_t ab = sb + st * STAGE_BYTES;
        const uint32_t bb = sb + 3 * STAGE_BYTES + st * STAGE_BYTES;
#pragma unroll
        for (int i = 0; i < 4; i++) {
            const int r = crow + 32 * i;
            cp16(ab + (r * PITCH + ccol) * 4, A + (long)(m0 + r) * lda + k0 + ccol);
            cp16(bb + (r * PITCH + ccol) * 4, B + (long)(n0 + r) * ldb + k0 + ccol);
        }
        asm volatile("cp.async.commit_group;" ::: "memory");
    };

    const uint32_t aRowOff = (uint32_t)(wm + lr + (sub & 1) * 8);
    const uint32_t aColOff = (uint32_t)((sub >> 1) * 4);
    const uint32_t bRowOff = (uint32_t)(wn + (sub >> 1) * 8 + lr);
    const uint32_t bColOff = (uint32_t)((sub & 1) * 4);

    const int KT = K / 32;

    issue(0); issue(1);

    for (int kt = 0; kt < KT; kt++) {
        asm volatile("cp.async.wait_group 1;" ::: "memory");
        __syncthreads();
        if (kt + 2 < KT) issue(kt + 2);
        else asm volatile("cp.async.commit_group;" ::: "memory");

        const int st = kt % 3;
        const uint32_t aSt = sb + st * STAGE_BYTES;
        const uint32_t bSt = sb + 3 * STAGE_BYTES + st * STAGE_BYTES;
#pragma unroll
        for (int s = 0; s < 4; s++) {
            const int ks = ((s + warp) & 3) * 8;   // per-warp slice rotation
            uint32_t a[4][4], b[4][2];
#pragma unroll
            for (int mb = 0; mb < 4; mb++) {
                const uint32_t addr = aSt + ((aRowOff + mb * 16) * PITCH + ks + aColOff) * 4;
                ldsm4(a[mb][0], a[mb][1], a[mb][2], a[mb][3], addr);
            }
#pragma unroll
            for (int np = 0; np < 2; np++) {
                const uint32_t addr = bSt + ((bRowOff + np * 16) * PITCH + ks + bColOff) * 4;
                ldsm4(b[np * 2][0], b[np * 2][1], b[np * 2 + 1][0], b[np * 2 + 1][1], addr);
            }
#pragma unroll
            for (int mi = 0; mi < 4; mi++)
#pragma unroll
                for (int ni = 0; ni < 4; ni++)
                    mma_tf32(acc[mi][ni], a[mi], b[ni]);
        }
    }

    if (MODE == 2) {
        // exp epilogue + deterministic per-CTA row sums
        float* part = (float*)smem;     // 4 x 128 floats; stages are dead after sync
        __syncthreads();                // all warps done reading smem stages
#pragma unroll
        for (int mi = 0; mi < 4; mi++) {
            const int row = m0 + wm + mi * 16 + gid;
            float e0s = 0.0f, e1s = 0.0f;
#pragma unroll
            for (int ni = 0; ni < 4; ni++) {
                const int col = n0 + wn + ni * 8 + tg * 2;
                float v0 = f2tf32f(__expf(acc[mi][ni][0] * alpha));
                float v1 = f2tf32f(__expf(acc[mi][ni][1] * alpha));
                float v2 = f2tf32f(__expf(acc[mi][ni][2] * alpha));
                float v3 = f2tf32f(__expf(acc[mi][ni][3] * alpha));
                *(float2*)(C + (long)row * ldc + col)       = make_float2(v0, v1);
                *(float2*)(C + (long)(row + 8) * ldc + col) = make_float2(v2, v3);
                e0s += v0 + v1; e1s += v2 + v3;
            }
            e0s += __shfl_xor_sync(0xffffffffu, e0s, 1);
            e0s += __shfl_xor_sync(0xffffffffu, e0s, 2);
            e1s += __shfl_xor_sync(0xffffffffu, e1s, 1);
            e1s += __shfl_xor_sync(0xffffffffu, e1s, 2);
            if (tg == 0) {
                part[(warp & 3) * 128 + wm + mi * 16 + gid]     = e0s;
                part[(warp & 3) * 128 + wm + mi * 16 + gid + 8] = e1s;
            }
        }
        __syncthreads();
        if (t < 128) {
            const float tot = part[t] + part[128 + t] + part[256 + t] + part[384 + t];
            psum[((long)z * SEQ + m0 + t) * NXBLK + blockIdx.x] = tot;
        }
        return;
    }

#pragma unroll
    for (int mi = 0; mi < 4; mi++) {
        const int row = m0 + wm + mi * 16 + gid;
        float i0 = 1.0f, i1 = 1.0f;
        if (MODE == 3) {
            i0 = rowinv[(long)z * SEQ + row];
            i1 = rowinv[(long)z * SEQ + row + 8];
        }
#pragma unroll
        for (int ni = 0; ni < 4; ni++) {
            const int col = n0 + wn + ni * 8 + tg * 2;
            float v0 = acc[mi][ni][0] * alpha, v1 = acc[mi][ni][1] * alpha;
            float v2 = acc[mi][ni][2] * alpha, v3 = acc[mi][ni][3] * alpha;
            if (MODE == 3) { v0 *= i0; v1 *= i0; v2 *= i1; v3 *= i1; }
            if (MODE == 1 || MODE == 3) {
                v0 = f2tf32f(v0); v1 = f2tf32f(v1);
                v2 = f2tf32f(v2); v3 = f2tf32f(v3);
            }
            *(float2*)(C + (long)row * ldc + col)       = make_float2(v0, v1);
            *(float2*)(C + (long)(row + 8) * ldc + col) = make_float2(v2, v3);
        }
    }
}

// ---------------------------------------------------------------------------
// rowinv[row] = 1 / sum_{x=0..15} psum[row][x]
// ---------------------------------------------------------------------------
__global__ void __launch_bounds__(256)
rowinv_reduce(const float* __restrict__ psum, float* __restrict__ rowinv)
{
    const long r = (long)blockIdx.x * 256 + threadIdx.x;
    const float4* p = (const float4*)(psum + r * NXBLK);
    float4 a = p[0], b = p[1], c = p[2], d = p[3];
    const float s = ((a.x + a.y) + (a.z + a.w)) + ((b.x + b.y) + (b.z + b.w))
                  + ((c.x + c.y) + (c.z + c.w)) + ((d.x + d.y) + (d.z + d.w));
    rowinv[r] = 1.0f / s;
}

// ---------------------------------------------------------------------------
// Elementwise tf32 rounding (for raw inputs)
// ---------------------------------------------------------------------------
__global__ void __launch_bounds__(256)
cvt_tf32(const float* __restrict__ in, float* __restrict__ out, int n4)
{
    const int i = blockIdx.x * 256 + threadIdx.x;
    if (i < n4) {
        float4 v = ((const float4*)in)[i];
        v.x = f2tf32f(v.x); v.y = f2tf32f(v.y);
        v.z = f2tf32f(v.z); v.w = f2tf32f(v.w);
        ((float4*)out)[i] = v;
    }
}

// ---------------------------------------------------------------------------
// V transpose: vT[z][h][t] = qkv[t*12288 + z*384 + 256 + h]
// ---------------------------------------------------------------------------
__global__ void __launch_bounds__(256)
transpose_v(const float* __restrict__ qkv, float* __restrict__ vT)
{
    __shared__ float tile[32][33];
    const int z  = blockIdx.z;
    const int t0 = blockIdx.x * 32;
    const int h0 = blockIdx.y * 32;
    const int x = threadIdx.x, y = threadIdx.y;
#pragma unroll
    for (int i = y; i < 32; i += 8)
        tile[i][x] = qkv[(long)(t0 + i) * RS + z * 384 + 2 * HN + h0 + x];
    __syncthreads();
#pragma unroll
    for (int i = y; i < 32; i += 8)
        vT[((long)z * HN + h0 + i) * SEQ + t0 + x] = tile[x][i];
}

// ---------------------------------------------------------------------------
extern "C" void kernel_launch(void* const* d_in, const int* in_sizes, int n_in,
                              void* d_out, int out_size)
{
    const float* hidden = (const float*)d_in[0];
    const float* w_qkv  = (const float*)d_in[1];
    const float* w_out  = (const float*)d_in[2];
    float* out = (float*)d_out;

    float *qkv, *scores, *vT, *ctx, *hidr, *wqkvr, *woutr, *psum, *rowinv;
    cudaGetSymbolAddress((void**)&qkv,    g_qkv);
    cudaGetSymbolAddress((void**)&scores, g_scores);
    cudaGetSymbolAddress((void**)&vT,     g_vT);
    cudaGetSymbolAddress((void**)&ctx,    g_ctx);
    cudaGetSymbolAddress((void**)&hidr,   g_hid);
    cudaGetSymbolAddress((void**)&wqkvr,  g_wqkv);
    cudaGetSymbolAddress((void**)&woutr,  g_wout);
    cudaGetSymbolAddress((void**)&psum,   g_psum);
    cudaGetSymbolAddress((void**)&rowinv, g_rowinv);

    cudaFuncSetAttribute((const void*)gemm_nt<0>, cudaFuncAttributeMaxDynamicSharedMemorySize, GEMM_SMEM);
    cudaFuncSetAttribute((const void*)gemm_nt<1>, cudaFuncAttributeMaxDynamicSharedMemorySize, GEMM_SMEM);
    cudaFuncSetAttribute((const void*)gemm_nt<2>, cudaFuncAttributeMaxDynamicSharedMemorySize, GEMM_SMEM);
    cudaFuncSetAttribute((const void*)gemm_nt<3>, cudaFuncAttributeMaxDynamicSharedMemorySize, GEMM_SMEM);

    const long SH = (long)SEQ * SEQ;

    // 0) pre-round raw inputs to tf32 values
    cvt_tf32<<<(MTOT * HID / 4 + 255) / 256, 256>>>(hidden, hidr, MTOT * HID / 4);
    cvt_tf32<<<(QKVN * HID / 4 + 255) / 256, 256>>>(w_qkv, wqkvr, QKVN * HID / 4);
    cvt_tf32<<<(HID * HID / 4 + 255) / 256, 256>>>(w_out, woutr, HID * HID / 4);

    // 1) QKV projection (rounded -> qkv holds tf32 values)
    gemm_nt<1><<<dim3(QKVN / 128, MTOT / 128, 1), 256, GEMM_SMEM>>>(
        hidr, HID, 0,  wqkvr, HID, 0,  qkv, QKVN, 0,  HID, 1.0f, nullptr, nullptr);

    // 2) V transpose for the PV GEMM
    transpose_v<<<dim3(SEQ / 32, HN / 32, NHEADS), dim3(32, 8)>>>(qkv, vT);

    // 3) scores[z] = exp(SCALE * Q_z K_z^T)  + per-block row sums
    gemm_nt<2><<<dim3(NXBLK, SEQ / 128, NHEADS), 256, GEMM_SMEM>>>(
        qkv,      BATCH * QKVN, 384,
        qkv + HN, BATCH * QKVN, 384,
        scores,   SEQ,          SH,
        HN, ATT_SCALE, psum, nullptr);

    // 4) rowinv = 1 / full row sum
    rowinv_reduce<<<NHEADS * SEQ / 256, 256>>>(psum, rowinv);

    // 5) ctx[z] = (exp(S) @ vT[z]^T) * rowinv  (normalized in epilogue, rounded)
    gemm_nt<3><<<dim3(HN / 128, SEQ / 128, NHEADS), 256, GEMM_SMEM>>>(
        scores, SEQ,         SH,
        vT,     SEQ,         (long)HN * SEQ,
        ctx,    BATCH * HID, HN,
        SEQ, 1.0f, nullptr, rowinv);

    // 6) output projection (plain fp32 out — final result)
    gemm_nt<0><<<dim3(HID / 128, MTOT / 128, 1), 256, GEMM_SMEM>>>(
        ctx, HID, 0,  woutr, HID, 0,  out, HID, 0,  HID, 1.0f, nullptr, nullptr);
}